// round 10
// baseline (speedup 1.0000x reference)
#include <cuda_runtime.h>
#include <cuda_fp16.h>
#include <math.h>
#include <stdint.h>

// Problem constants
#define B_  2
#define S_  2048
#define DM_ 2048
#define NH_ 16
#define HD_ 128
#define BS_ (B_ * S_)
#define SCALE_ 0.08838834764831845f   // 1/sqrt(128)
#define GK 2048
#define GN 2048

// ---------------------------------------------------------------------------
// Scratch
// ---------------------------------------------------------------------------
__device__ __half g_qh[B_ * NH_ * S_ * HD_];
__device__ __half g_kh[B_ * NH_ * S_ * HD_];
__device__ __half g_vh[B_ * NH_ * S_ * HD_];
__device__ __half g_ctxh[BS_ * DM_];
__device__ __half g_ah[BS_ * DM_];
__device__ unsigned g_wt[4][(DM_ / 2) * DM_];  // k-pair-interleaved half2 W
__device__ float g_cos[S_ * (HD_ / 2)];
__device__ float g_sin[S_ * (HD_ / 2)];

// ---------------------------------------------------------------------------
// RoPE table (double precision)
// ---------------------------------------------------------------------------
__global__ void rope_table_kernel() {
    int idx = blockIdx.x * blockDim.x + threadIdx.x;
    if (idx >= S_ * (HD_ / 2)) return;
    int s = idx / (HD_ / 2);
    int i = idx % (HD_ / 2);
    double inv_freq = exp(-((double)(2 * i) / (double)HD_) * log(10000.0));
    double ang = (double)s * inv_freq;
    g_cos[idx] = (float)cos(ang);
    g_sin[idx] = (float)sin(ang);
}

__device__ __forceinline__ unsigned h2u(float lo, float hi) {
    __half2 h = __floats2half2_rn(lo, hi);
    return *(unsigned*)&h;
}

// hs f32 -> half (8 elems/thread)
__global__ void cvt_a_kernel(const float* __restrict__ in,
                             __half* __restrict__ out, int n8) {
    int i = blockIdx.x * blockDim.x + threadIdx.x;
    if (i >= n8) return;
    float4 f0 = ((const float4*)in)[2 * i];
    float4 f1 = ((const float4*)in)[2 * i + 1];
    uint4 u;
    u.x = h2u(f0.x, f0.y); u.y = h2u(f0.z, f0.w);
    u.z = h2u(f1.x, f1.y); u.w = h2u(f1.z, f1.w);
    ((uint4*)out)[i] = u;
}

// W[k][n] f32 -> Wt[k2][n] = half2(W[2k2][n], W[2k2+1][n]); z selects weight
__global__ void cvt_w_kernel(const float* __restrict__ W0,
                             const float* __restrict__ W1,
                             const float* __restrict__ W2,
                             const float* __restrict__ W3,
                             unsigned* __restrict__ Wt) {
    int idx = blockIdx.x * blockDim.x + threadIdx.x;
    if (idx >= (GK / 2) * (GN / 4)) return;
    const int z = blockIdx.z;
    const float* W = (z == 0) ? W0 : (z == 1) ? W1 : (z == 2) ? W2 : W3;
    unsigned* Wz = Wt + (size_t)z * (GK / 2) * GN;
    int k2 = idx / (GN / 4);
    int n  = (idx % (GN / 4)) * 4;
    float4 f0 = *(const float4*)(W + (size_t)(2 * k2) * GN + n);
    float4 f1 = *(const float4*)(W + (size_t)(2 * k2 + 1) * GN + n);
    uint4 u;
    u.x = h2u(f0.x, f1.x); u.y = h2u(f0.y, f1.y);
    u.z = h2u(f0.z, f1.z); u.w = h2u(f0.w, f1.w);
    *(uint4*)(Wz + (size_t)k2 * GN + n) = u;
}

__device__ __forceinline__ uint32_t smem_u32(const void* p) {
    uint32_t a;
    asm("{ .reg .u64 t; cvta.to.shared.u64 t, %1; cvt.u32.u64 %0, t; }"
        : "=r"(a) : "l"(p));
    return a;
}

#define CP_ASYNC16(dst, src)                                                  \
    asm volatile("cp.async.cg.shared.global [%0], [%1], 16;"                  \
                 :: "r"(dst), "l"(src) : "memory")

#define MMA_F16(Cc, a0, a1, a2, a3, b0, b1)                                   \
    asm volatile(                                                             \
        "mma.sync.aligned.m16n8k16.row.col.f32.f16.f16.f32 "                  \
        "{%0,%1,%2,%3}, {%4,%5,%6,%7}, {%8,%9}, {%0,%1,%2,%3};"               \
        : "+f"((Cc)[0]), "+f"((Cc)[1]), "+f"((Cc)[2]), "+f"((Cc)[3])          \
        : "r"(a0), "r"(a1), "r"(a2), "r"(a3), "r"(b0), "r"(b1))

// ---------------------------------------------------------------------------
// FP16 GEMM with cp.async: 128x128 CTA, 128 thr, 4 warps of 64x64, k16 MMA,
// 3-stage pipeline. As2 [m][k/2] stride 20 words; Bs2 [k2][n] stride 136.
// mode 0: rope+scale -> half scatter (Q)  mode 3: rope -> half scatter (K)
// mode 1: half scatter (V)                mode 2: float row-major (O proj)
// mode0 < 0: derive from blockIdx.z.
// ---------------------------------------------------------------------------
#define ASTRIDE 20
#define BSTRIDE 136
#define ABYTES  (128 * ASTRIDE * 4)           // 10240
#define STAGEB  (ABYTES + 16 * BSTRIDE * 4)   // 18944
#define NKB (GK / 32)

__global__ __launch_bounds__(128, 2) void hgemm2_kernel(
    const __half* __restrict__ Ah,
    const unsigned* __restrict__ Wt0, const unsigned* __restrict__ Wt1,
    const unsigned* __restrict__ Wt2,
    const float* __restrict__ b0p, const float* __restrict__ b1p,
    const float* __restrict__ b2p,
    void* __restrict__ C0, void* __restrict__ C1, void* __restrict__ C2,
    int mode0)
{
    extern __shared__ unsigned char smraw[];

    const unsigned* Wt; const float* bias; void* C; int mode;
    if (mode0 >= 0) { Wt = Wt0; bias = b0p; C = C0; mode = mode0; }
    else {
        const int z = blockIdx.z;
        Wt   = (z == 0) ? Wt0 : (z == 1) ? Wt1 : Wt2;
        bias = (z == 0) ? b0p : (z == 1) ? b1p : b2p;
        C    = (z == 0) ? C0 : (z == 1) ? C1 : C2;
        mode = (z == 0) ? 0 : (z == 1) ? 3 : 1;
    }

    const int tid  = threadIdx.x;
    const int lane = tid & 31, wid = tid >> 5;
    const int wm = wid >> 1, wn = wid & 1;           // 2 x 2 warps
    const int gid = lane >> 2, tig = lane & 3;
    const int m0 = blockIdx.y * 128, n0 = blockIdx.x * 128;

    const uint32_t sb = smem_u32(smraw);

    // cp.async: A = 128 rows x 64B (1 row/thread, 4x16B);
    //           B = 16 rows x 512B (8 thr/row, 64B each)
    const __half* asrc0 = Ah + (size_t)(m0 + tid) * GK;
    const int brow = tid >> 3, bc = tid & 7;
    const unsigned* bsrc0 = Wt + (size_t)brow * GN + n0 + bc * 16;

    auto issue = [&](int ib) {
        const uint32_t base = sb + (ib % 3) * STAGEB;
        const __half* as = asrc0 + ib * 32;
        #pragma unroll
        for (int j = 0; j < 4; j++)
            CP_ASYNC16(base + tid * 80 + j * 16, as + j * 8);
        const unsigned* bs = bsrc0 + (size_t)(ib * 16) * GN;
        #pragma unroll
        for (int j = 0; j < 4; j++)
            CP_ASYNC16(base + ABYTES + brow * 544 + bc * 64 + j * 16, bs + j * 4);
        asm volatile("cp.async.commit_group;" ::: "memory");
    };
    issue(0);
    issue(1);

    float acc[4][8][4];
    #pragma unroll
    for (int mi = 0; mi < 4; mi++)
        #pragma unroll
        for (int ni = 0; ni < 8; ni++)
            #pragma unroll
            for (int u = 0; u < 4; u++) acc[mi][ni][u] = 0.f;

    for (int ib = 0; ib < NKB; ib++) {
        if (ib + 2 < NKB)
            asm volatile("cp.async.wait_group 1;" ::: "memory");
        else
            asm volatile("cp.async.wait_group 0;" ::: "memory");
        __syncthreads();
        if (ib + 2 < NKB) issue(ib + 2);

        const unsigned* As2 = (const unsigned*)(smraw + (ib % 3) * STAGEB);
        const unsigned* Bs2 = (const unsigned*)(smraw + (ib % 3) * STAGEB + ABYTES);

        #pragma unroll
        for (int kk2 = 0; kk2 < 16; kk2 += 8) {
            unsigned af[4][4], bf[8][2];
            #pragma unroll
            for (int mi = 0; mi < 4; mi++) {
                const int mr = wm * 64 + mi * 16 + gid;
                af[mi][0] = As2[mr * ASTRIDE + kk2 + tig];
                af[mi][1] = As2[(mr + 8) * ASTRIDE + kk2 + tig];
                af[mi][2] = As2[mr * ASTRIDE + kk2 + tig + 4];
                af[mi][3] = As2[(mr + 8) * ASTRIDE + kk2 + tig + 4];
            }
            #pragma unroll
            for (int ni = 0; ni < 8; ni++) {
                const int nc = wn * 64 + ni * 8 + gid;
                bf[ni][0] = Bs2[(kk2 + tig) * BSTRIDE + nc];
                bf[ni][1] = Bs2[(kk2 + tig + 4) * BSTRIDE + nc];
            }
            #pragma unroll
            for (int mi = 0; mi < 4; mi++)
                #pragma unroll
                for (int ni = 0; ni < 8; ni++)
                    MMA_F16(acc[mi][ni], af[mi][0], af[mi][1], af[mi][2],
                            af[mi][3], bf[ni][0], bf[ni][1]);
        }
        __syncthreads();
    }

    // Epilogue
    #pragma unroll
    for (int ni = 0; ni < 8; ni++) {
        const int c = n0 + wn * 64 + ni * 8 + tig * 2;
        const float bv0 = bias[c], bv1 = bias[c + 1];
        #pragma unroll
        for (int mi = 0; mi < 4; mi++) {
            #pragma unroll
            for (int half_ = 0; half_ < 2; half_++) {
                const int r = m0 + wm * 64 + mi * 16 + gid + half_ * 8;
                float v0 = acc[mi][ni][half_ * 2 + 0] + bv0;
                float v1 = acc[mi][ni][half_ * 2 + 1] + bv1;
                const int bb = r >> 11;
                const int s  = r & (S_ - 1);
                if (mode == 0 || mode == 3) {
                    const int pi = (c & (HD_ - 1)) >> 1;
                    const float cs = g_cos[s * (HD_ / 2) + pi];
                    const float sn = g_sin[s * (HD_ / 2) + pi];
                    const float e = v0, o = v1;
                    v0 = e * cs - o * sn;
                    v1 = o * cs + e * sn;
                    if (mode == 0) { v0 *= SCALE_; v1 *= SCALE_; }
                }
                if (mode != 2) {
                    const int h = (c >> 7) & (NH_ - 1);
                    const int d = c & (HD_ - 1);
                    __half* dst = (__half*)C +
                        (size_t)((bb * NH_ + h) * S_ + s) * HD_ + d;
                    *(unsigned*)dst = h2u(v0, v1);
                } else {
                    float2 val; val.x = v0; val.y = v1;
                    *(float2*)((float*)C + (size_t)r * GN + c) = val;
                }
            }
        }
    }
}

// ---------------------------------------------------------------------------
// Flash attention (causal), fp16 m16n8k16, half I/O (unchanged from R9).
// ---------------------------------------------------------------------------
#define QST 68
#define VST 136
#define QWORDS (64 * QST)

__global__ __launch_bounds__(128) void attn_h_kernel(
    const __half* __restrict__ q, const __half* __restrict__ k,
    const __half* __restrict__ v, __half* __restrict__ ctx)
{
    extern __shared__ unsigned smu[];
    unsigned* Qs2 = smu;
    unsigned* Ks2 = Qs2 + QWORDS;
    unsigned* Vs2 = Ks2 + QWORDS;

    const int tid  = threadIdx.x;
    const int lane = tid & 31, wid = tid >> 5;
    const int gid = lane >> 2, tig = lane & 3;
    const int bh = blockIdx.y;
    const int qt = gridDim.x - 1 - blockIdx.x;
    const int q0 = qt * 64;
    const int m0w = wid * 16;

    const __half* qp = q + ((size_t)bh * S_ + q0) * HD_;
    const __half* kb = k + (size_t)bh * S_ * HD_;
    const __half* vb = v + (size_t)bh * S_ * HD_;

    for (int t = tid; t < 64 * 16; t += 128) {
        int r = t >> 4, c = (t & 15) * 8;
        *(uint4*)&Qs2[r * QST + c / 2] = *(const uint4*)&qp[r * HD_ + c];
    }

    float oacc[16][4];
    #pragma unroll
    for (int ni = 0; ni < 16; ni++)
        #pragma unroll
        for (int u = 0; u < 4; u++) oacc[ni][u] = 0.f;
    float mx0 = -1e30f, mx1 = -1e30f, ls0 = 0.f, ls1 = 0.f;

    const int nkv = qt + 1;
    for (int kt = 0; kt < nkv; kt++) {
        const int k0 = kt * 64;
        __syncthreads();
        const __half* kp = kb + (size_t)k0 * HD_;
        const __half* vp = vb + (size_t)k0 * HD_;
        for (int t = tid; t < 64 * 16; t += 128) {
            int r = t >> 4, c = (t & 15) * 8;
            *(uint4*)&Ks2[r * QST + c / 2] = *(const uint4*)&kp[r * HD_ + c];
        }
        for (int t = tid; t < 32 * 32; t += 128) {
            int s2 = t >> 5, c = (t & 31) * 4;
            uint2 e = *(const uint2*)&vp[(2 * s2) * HD_ + c];
            uint2 o = *(const uint2*)&vp[(2 * s2 + 1) * HD_ + c];
            uint4 u;
            u.x = __byte_perm(e.x, o.x, 0x5410);
            u.y = __byte_perm(e.x, o.x, 0x7632);
            u.z = __byte_perm(e.y, o.y, 0x5410);
            u.w = __byte_perm(e.y, o.y, 0x7632);
            *(uint4*)&Vs2[s2 * VST + c] = u;
        }
        __syncthreads();

        float sacc[8][4];
        #pragma unroll
        for (int ni = 0; ni < 8; ni++)
            #pragma unroll
            for (int u = 0; u < 4; u++) sacc[ni][u] = 0.f;

        #pragma unroll
        for (int ks = 0; ks < 8; ks++) {
            const int kw = ks * 8;
            unsigned a0 = Qs2[(m0w + gid) * QST + kw + tig];
            unsigned a1 = Qs2[(m0w + gid + 8) * QST + kw + tig];
            unsigned a2 = Qs2[(m0w + gid) * QST + kw + tig + 4];
            unsigned a3 = Qs2[(m0w + gid + 8) * QST + kw + tig + 4];
            #pragma unroll
            for (int ni = 0; ni < 8; ni++) {
                unsigned b0 = Ks2[(ni * 8 + gid) * QST + kw + tig];
                unsigned b1 = Ks2[(ni * 8 + gid) * QST + kw + tig + 4];
                MMA_F16(sacc[ni], a0, a1, a2, a3, b0, b1);
            }
        }

        if (kt == nkv - 1) {
            const int row0 = q0 + m0w + gid;
            #pragma unroll
            for (int ni = 0; ni < 8; ni++) {
                const int col = k0 + ni * 8 + tig * 2;
                if (col > row0)     sacc[ni][0] = -1e30f;
                if (col + 1 > row0) sacc[ni][1] = -1e30f;
                if (col > row0 + 8)     sacc[ni][2] = -1e30f;
                if (col + 1 > row0 + 8) sacc[ni][3] = -1e30f;
            }
        }

        float rm0 = -1e30f, rm1 = -1e30f;
        #pragma unroll
        for (int ni = 0; ni < 8; ni++) {
            rm0 = fmaxf(rm0, fmaxf(sacc[ni][0], sacc[ni][1]));
            rm1 = fmaxf(rm1, fmaxf(sacc[ni][2], sacc[ni][3]));
        }
        rm0 = fmaxf(rm0, __shfl_xor_sync(0xffffffffu, rm0, 1));
        rm0 = fmaxf(rm0, __shfl_xor_sync(0xffffffffu, rm0, 2));
        rm1 = fmaxf(rm1, __shfl_xor_sync(0xffffffffu, rm1, 1));
        rm1 = fmaxf(rm1, __shfl_xor_sync(0xffffffffu, rm1, 2));

        const float mn0 = fmaxf(mx0, rm0), mn1 = fmaxf(mx1, rm1);
        const float f0 = __expf(mx0 - mn0), f1 = __expf(mx1 - mn1);
        float rs0 = 0.f, rs1 = 0.f;
        #pragma unroll
        for (int ni = 0; ni < 8; ni++) {
            float p0 = __expf(sacc[ni][0] - mn0);
            float p1 = __expf(sacc[ni][1] - mn0);
            float p2 = __expf(sacc[ni][2] - mn1);
            float p3 = __expf(sacc[ni][3] - mn1);
            sacc[ni][0] = p0; sacc[ni][1] = p1;
            sacc[ni][2] = p2; sacc[ni][3] = p3;
            rs0 += p0 + p1; rs1 += p2 + p3;
        }
        rs0 += __shfl_xor_sync(0xffffffffu, rs0, 1);
        rs0 += __shfl_xor_sync(0xffffffffu, rs0, 2);
        rs1 += __shfl_xor_sync(0xffffffffu, rs1, 1);
        rs1 += __shfl_xor_sync(0xffffffffu, rs1, 2);
        ls0 = ls0 * f0 + rs0; ls1 = ls1 * f1 + rs1;
        mx0 = mn0; mx1 = mn1;

        #pragma unroll
        for (int ni = 0; ni < 16; ni++) {
            oacc[ni][0] *= f0; oacc[ni][1] *= f0;
            oacc[ni][2] *= f1; oacc[ni][3] *= f1;
        }

        #pragma unroll
        for (int j = 0; j < 4; j++) {
            unsigned pa0 = h2u(sacc[2 * j][0], sacc[2 * j][1]);
            unsigned pa1 = h2u(sacc[2 * j][2], sacc[2 * j][3]);
            unsigned pa2 = h2u(sacc[2 * j + 1][0], sacc[2 * j + 1][1]);
            unsigned pa3 = h2u(sacc[2 * j + 1][2], sacc[2 * j + 1][3]);
            #pragma unroll
            for (int ni = 0; ni < 16; ni++) {
                const int nc = ni * 8 + gid;
                unsigned b0 = Vs2[(8 * j + tig) * VST + nc];
                unsigned b1 = Vs2[(8 * j + 4 + tig) * VST + nc];
                MMA_F16(oacc[ni], pa0, pa1, pa2, pa3, b0, b1);
            }
        }
    }

    const float inv0 = 1.f / ls0, inv1 = 1.f / ls1;
    const int b = bh >> 4, h = bh & 15;
    const int s0 = q0 + m0w + gid;
    #pragma unroll
    for (int ni = 0; ni < 16; ni++) {
        const int col = ni * 8 + tig * 2;
        *(unsigned*)&ctx[(size_t)(b * S_ + s0) * DM_ + h * HD_ + col] =
            h2u(oacc[ni][0] * inv0, oacc[ni][1] * inv0);
        *(unsigned*)&ctx[(size_t)(b * S_ + s0 + 8) * DM_ + h * HD_ + col] =
            h2u(oacc[ni][2] * inv1, oacc[ni][3] * inv1);
    }
}

// ---------------------------------------------------------------------------
// Launch
// ---------------------------------------------------------------------------
extern "C" void kernel_launch(void* const* d_in, const int* in_sizes, int n_in,
                              void* d_out, int out_size)
{
    const float* hs = (const float*)d_in[0];
    const float* Wq = (const float*)d_in[1];
    const float* bq = (const float*)d_in[2];
    const float* Wk = (const float*)d_in[3];
    const float* bk = (const float*)d_in[4];
    const float* Wv = (const float*)d_in[5];
    const float* bv = (const float*)d_in[6];
    const float* Wo = (const float*)d_in[7];
    const float* bo = (const float*)d_in[8];
    float* out = (float*)d_out;

    __half *qd, *kd, *vd, *ctxd, *ahd;
    unsigned* wtd;
    cudaGetSymbolAddress((void**)&qd,   g_qh);
    cudaGetSymbolAddress((void**)&kd,   g_kh);
    cudaGetSymbolAddress((void**)&vd,   g_vh);
    cudaGetSymbolAddress((void**)&ctxd, g_ctxh);
    cudaGetSymbolAddress((void**)&ahd,  g_ah);
    cudaGetSymbolAddress((void**)&wtd,  g_wt);
    unsigned* wq_t = wtd + 0 * (size_t)(DM_ / 2) * DM_;
    unsigned* wk_t = wtd + 1 * (size_t)(DM_ / 2) * DM_;
    unsigned* wv_t = wtd + 2 * (size_t)(DM_ / 2) * DM_;
    unsigned* wo_t = wtd + 3 * (size_t)(DM_ / 2) * DM_;

    const int gemm_smem = 3 * STAGEB;
    const int attn_smem = (2 * QWORDS + 32 * VST) * (int)sizeof(unsigned);
    static int smem_set = 0;
    if (!smem_set) {
        cudaFuncSetAttribute(hgemm2_kernel,
                             cudaFuncAttributeMaxDynamicSharedMemorySize,
                             gemm_smem);
        cudaFuncSetAttribute(attn_h_kernel,
                             cudaFuncAttributeMaxDynamicSharedMemorySize,
                             attn_smem);
        smem_set = 1;
    }

    rope_table_kernel<<<(S_ * (HD_ / 2) + 255) / 256, 256>>>();

    // Prepass: hs -> half, all W -> k-pair-interleaved half2 (one launch)
    const int na8 = BS_ * DM_ / 8;
    const int nw  = (GK / 2) * (GN / 4);
    cvt_a_kernel<<<(na8 + 255) / 256, 256>>>(hs, ahd, na8);
    dim3 wgrid((nw + 255) / 256, 1, 4);
    cvt_w_kernel<<<wgrid, 256>>>(Wq, Wk, Wv, Wo, wtd);

    // Merged QKV
    dim3 qkvgrid(GN / 128, 4096 / 128, 3);
    hgemm2_kernel<<<qkvgrid, 128, gemm_smem>>>(
        ahd, wq_t, wk_t, wv_t, bq, bk, bv, qd, kd, vd, -1);

    dim3 agrid(S_ / 64, B_ * NH_);
    attn_h_kernel<<<agrid, 128, attn_smem>>>(qd, kd, vd, ctxd);

    dim3 ogrid(GN / 128, 4096 / 128, 1);
    hgemm2_kernel<<<ogrid, 128, gemm_smem>>>(
        ctxd, wo_t, nullptr, nullptr, bo, nullptr, nullptr, out, nullptr,
        nullptr, 2);
}

// round 11
// speedup vs baseline: 1.0640x; 1.0640x over previous
#include <cuda_runtime.h>
#include <cuda_fp16.h>
#include <math.h>
#include <stdint.h>

// Problem constants
#define B_  2
#define S_  2048
#define DM_ 2048
#define NH_ 16
#define HD_ 128
#define BS_ (B_ * S_)
#define SCALE_ 0.08838834764831845f   // 1/sqrt(128)
#define GK 2048
#define GN 2048

// ---------------------------------------------------------------------------
// Scratch
// ---------------------------------------------------------------------------
__device__ __half g_qh[B_ * NH_ * S_ * HD_];
__device__ __half g_kh[B_ * NH_ * S_ * HD_];
__device__ __half g_vh[B_ * NH_ * S_ * HD_];
__device__ __half g_ctxh[BS_ * DM_];
__device__ __half g_ah[BS_ * DM_];
__device__ unsigned g_wt[4][(DM_ / 2) * DM_];  // k-pair-interleaved half2 W
__device__ float g_cos[S_ * (HD_ / 2)];
__device__ float g_sin[S_ * (HD_ / 2)];

// ---------------------------------------------------------------------------
// RoPE table (double precision)
// ---------------------------------------------------------------------------
__global__ void rope_table_kernel() {
    int idx = blockIdx.x * blockDim.x + threadIdx.x;
    if (idx >= S_ * (HD_ / 2)) return;
    int s = idx / (HD_ / 2);
    int i = idx % (HD_ / 2);
    double inv_freq = exp(-((double)(2 * i) / (double)HD_) * log(10000.0));
    double ang = (double)s * inv_freq;
    g_cos[idx] = (float)cos(ang);
    g_sin[idx] = (float)sin(ang);
}

__device__ __forceinline__ unsigned h2u(float lo, float hi) {
    __half2 h = __floats2half2_rn(lo, hi);
    return *(unsigned*)&h;
}

// hs f32 -> half (8 elems/thread)
__global__ void cvt_a_kernel(const float* __restrict__ in,
                             __half* __restrict__ out, int n8) {
    int i = blockIdx.x * blockDim.x + threadIdx.x;
    if (i >= n8) return;
    float4 f0 = ((const float4*)in)[2 * i];
    float4 f1 = ((const float4*)in)[2 * i + 1];
    uint4 u;
    u.x = h2u(f0.x, f0.y); u.y = h2u(f0.z, f0.w);
    u.z = h2u(f1.x, f1.y); u.w = h2u(f1.z, f1.w);
    ((uint4*)out)[i] = u;
}

// W[k][n] f32 -> Wt[k2][n] = half2(W[2k2][n], W[2k2+1][n]); z selects weight
__global__ void cvt_w_kernel(const float* __restrict__ W0,
                             const float* __restrict__ W1,
                             const float* __restrict__ W2,
                             const float* __restrict__ W3,
                             unsigned* __restrict__ Wt) {
    int idx = blockIdx.x * blockDim.x + threadIdx.x;
    if (idx >= (GK / 2) * (GN / 4)) return;
    const int z = blockIdx.z;
    const float* W = (z == 0) ? W0 : (z == 1) ? W1 : (z == 2) ? W2 : W3;
    unsigned* Wz = Wt + (size_t)z * (GK / 2) * GN;
    int k2 = idx / (GN / 4);
    int n  = (idx % (GN / 4)) * 4;
    float4 f0 = *(const float4*)(W + (size_t)(2 * k2) * GN + n);
    float4 f1 = *(const float4*)(W + (size_t)(2 * k2 + 1) * GN + n);
    uint4 u;
    u.x = h2u(f0.x, f1.x); u.y = h2u(f0.y, f1.y);
    u.z = h2u(f0.z, f1.z); u.w = h2u(f0.w, f1.w);
    *(uint4*)(Wz + (size_t)k2 * GN + n) = u;
}

__device__ __forceinline__ uint32_t smem_u32(const void* p) {
    uint32_t a;
    asm("{ .reg .u64 t; cvta.to.shared.u64 t, %1; cvt.u32.u64 %0, t; }"
        : "=r"(a) : "l"(p));
    return a;
}

#define CP_ASYNC16(dst, src)                                                  \
    asm volatile("cp.async.cg.shared.global [%0], [%1], 16;"                  \
                 :: "r"(dst), "l"(src) : "memory")

#define MMA_F16(Cc, a0, a1, a2, a3, b0, b1)                                   \
    asm volatile(                                                             \
        "mma.sync.aligned.m16n8k16.row.col.f32.f16.f16.f32 "                  \
        "{%0,%1,%2,%3}, {%4,%5,%6,%7}, {%8,%9}, {%0,%1,%2,%3};"               \
        : "+f"((Cc)[0]), "+f"((Cc)[1]), "+f"((Cc)[2]), "+f"((Cc)[3])          \
        : "r"(a0), "r"(a1), "r"(a2), "r"(a3), "r"(b0), "r"(b1))

// ---------------------------------------------------------------------------
// FP16 GEMM with cp.async: 128x128 CTA, 256 thr, 8 warps of 64x32, k16 MMA,
// BK=64 (half the barriers of BK=32), 3-stage pipeline.
// As2 [m][k2] stride 36 words (32 used); Bs2 [k2][n] stride 136 words.
// mode 0: rope+scale -> half scatter (Q)  mode 3: rope -> half scatter (K)
// mode 1: half scatter (V)                mode 2: float row-major (O proj)
// mode0 < 0: derive from blockIdx.z.
// ---------------------------------------------------------------------------
#define ASTRIDE 36
#define BSTRIDE 136
#define ABYTES  (128 * ASTRIDE * 4)           // 18432
#define STAGEB  (ABYTES + 32 * BSTRIDE * 4)   // 35840
#define NKB (GK / 64)                          // 32

__global__ __launch_bounds__(256) void hgemm2_kernel(
    const __half* __restrict__ Ah,
    const unsigned* __restrict__ Wt0, const unsigned* __restrict__ Wt1,
    const unsigned* __restrict__ Wt2,
    const float* __restrict__ b0p, const float* __restrict__ b1p,
    const float* __restrict__ b2p,
    void* __restrict__ C0, void* __restrict__ C1, void* __restrict__ C2,
    int mode0)
{
    extern __shared__ unsigned char smraw[];

    const unsigned* Wt; const float* bias; void* C; int mode;
    if (mode0 >= 0) { Wt = Wt0; bias = b0p; C = C0; mode = mode0; }
    else {
        const int z = blockIdx.z;
        Wt   = (z == 0) ? Wt0 : (z == 1) ? Wt1 : Wt2;
        bias = (z == 0) ? b0p : (z == 1) ? b1p : b2p;
        C    = (z == 0) ? C0 : (z == 1) ? C1 : C2;
        mode = (z == 0) ? 0 : (z == 1) ? 3 : 1;
    }

    const int tid  = threadIdx.x;
    const int lane = tid & 31, wid = tid >> 5;
    const int warpM = wid >> 2, warpN = wid & 3;     // 2 x 4
    const int gid = lane >> 2, tig = lane & 3;
    const int m0 = blockIdx.y * 128, n0 = blockIdx.x * 128;

    const uint32_t sb = smem_u32(smraw);

    // cp.async: A = 128 rows x 128B (2 thr/row, 64B each);
    //           B = 32 k2-rows x 512B (8 thr/row, 64B each)
    const int arow = tid >> 1, ac = tid & 1;
    const __half* asrc0 = Ah + (size_t)(m0 + arow) * GK + ac * 32;
    const int brow = tid >> 3, bc = tid & 7;
    const unsigned* bsrc0 = Wt + (size_t)brow * GN + n0 + bc * 16;

    auto issue = [&](int ib) {
        const uint32_t base = sb + (ib % 3) * STAGEB;
        const __half* as = asrc0 + ib * 64;
        #pragma unroll
        for (int j = 0; j < 4; j++)
            CP_ASYNC16(base + arow * 144 + ac * 64 + j * 16, as + j * 8);
        const unsigned* bs = bsrc0 + (size_t)(ib * 32) * GN;
        #pragma unroll
        for (int j = 0; j < 4; j++)
            CP_ASYNC16(base + ABYTES + brow * 544 + bc * 64 + j * 16, bs + j * 4);
        asm volatile("cp.async.commit_group;" ::: "memory");
    };
    issue(0);
    issue(1);

    float acc[4][4][4];
    #pragma unroll
    for (int mi = 0; mi < 4; mi++)
        #pragma unroll
        for (int ni = 0; ni < 4; ni++)
            #pragma unroll
            for (int u = 0; u < 4; u++) acc[mi][ni][u] = 0.f;

    for (int ib = 0; ib < NKB; ib++) {
        if (ib + 2 < NKB)
            asm volatile("cp.async.wait_group 1;" ::: "memory");
        else
            asm volatile("cp.async.wait_group 0;" ::: "memory");
        __syncthreads();
        if (ib + 2 < NKB) issue(ib + 2);

        const unsigned* As2 = (const unsigned*)(smraw + (ib % 3) * STAGEB);
        const unsigned* Bs2 = (const unsigned*)(smraw + (ib % 3) * STAGEB + ABYTES);

        #pragma unroll
        for (int kk2 = 0; kk2 < 32; kk2 += 8) {    // four k16 steps
            unsigned af[4][4], bf[4][2];
            #pragma unroll
            for (int mi = 0; mi < 4; mi++) {
                const int mr = warpM * 64 + mi * 16 + gid;
                af[mi][0] = As2[mr * ASTRIDE + kk2 + tig];
                af[mi][1] = As2[(mr + 8) * ASTRIDE + kk2 + tig];
                af[mi][2] = As2[mr * ASTRIDE + kk2 + tig + 4];
                af[mi][3] = As2[(mr + 8) * ASTRIDE + kk2 + tig + 4];
            }
            #pragma unroll
            for (int ni = 0; ni < 4; ni++) {
                const int nc = warpN * 32 + ni * 8 + gid;
                bf[ni][0] = Bs2[(kk2 + tig) * BSTRIDE + nc];
                bf[ni][1] = Bs2[(kk2 + tig + 4) * BSTRIDE + nc];
            }
            #pragma unroll
            for (int mi = 0; mi < 4; mi++)
                #pragma unroll
                for (int ni = 0; ni < 4; ni++)
                    MMA_F16(acc[mi][ni], af[mi][0], af[mi][1], af[mi][2],
                            af[mi][3], bf[ni][0], bf[ni][1]);
        }
        __syncthreads();
    }

    // Epilogue
    #pragma unroll
    for (int ni = 0; ni < 4; ni++) {
        const int c = n0 + warpN * 32 + ni * 8 + tig * 2;
        const float bv0 = bias[c], bv1 = bias[c + 1];
        #pragma unroll
        for (int mi = 0; mi < 4; mi++) {
            #pragma unroll
            for (int half_ = 0; half_ < 2; half_++) {
                const int r = m0 + warpM * 64 + mi * 16 + gid + half_ * 8;
                float v0 = acc[mi][ni][half_ * 2 + 0] + bv0;
                float v1 = acc[mi][ni][half_ * 2 + 1] + bv1;
                const int bb = r >> 11;
                const int s  = r & (S_ - 1);
                if (mode == 0 || mode == 3) {
                    const int pi = (c & (HD_ - 1)) >> 1;
                    const float cs = g_cos[s * (HD_ / 2) + pi];
                    const float sn = g_sin[s * (HD_ / 2) + pi];
                    const float e = v0, o = v1;
                    v0 = e * cs - o * sn;
                    v1 = o * cs + e * sn;
                    if (mode == 0) { v0 *= SCALE_; v1 *= SCALE_; }
                }
                if (mode != 2) {
                    const int h = (c >> 7) & (NH_ - 1);
                    const int d = c & (HD_ - 1);
                    __half* dst = (__half*)C +
                        (size_t)((bb * NH_ + h) * S_ + s) * HD_ + d;
                    *(unsigned*)dst = h2u(v0, v1);
                } else {
                    float2 val; val.x = v0; val.y = v1;
                    *(float2*)((float*)C + (size_t)r * GN + c) = val;
                }
            }
        }
    }
}

// ---------------------------------------------------------------------------
// Flash attention (causal), fp16 m16n8k16, half I/O (R9-proven, unchanged).
// ---------------------------------------------------------------------------
#define QST 68
#define VST 136
#define QWORDS (64 * QST)

__global__ __launch_bounds__(128) void attn_h_kernel(
    const __half* __restrict__ q, const __half* __restrict__ k,
    const __half* __restrict__ v, __half* __restrict__ ctx)
{
    extern __shared__ unsigned smu[];
    unsigned* Qs2 = smu;
    unsigned* Ks2 = Qs2 + QWORDS;
    unsigned* Vs2 = Ks2 + QWORDS;

    const int tid  = threadIdx.x;
    const int lane = tid & 31, wid = tid >> 5;
    const int gid = lane >> 2, tig = lane & 3;
    const int bh = blockIdx.y;
    const int qt = gridDim.x - 1 - blockIdx.x;
    const int q0 = qt * 64;
    const int m0w = wid * 16;

    const __half* qp = q + ((size_t)bh * S_ + q0) * HD_;
    const __half* kb = k + (size_t)bh * S_ * HD_;
    const __half* vb = v + (size_t)bh * S_ * HD_;

    for (int t = tid; t < 64 * 16; t += 128) {
        int r = t >> 4, c = (t & 15) * 8;
        *(uint4*)&Qs2[r * QST + c / 2] = *(const uint4*)&qp[r * HD_ + c];
    }

    float oacc[16][4];
    #pragma unroll
    for (int ni = 0; ni < 16; ni++)
        #pragma unroll
        for (int u = 0; u < 4; u++) oacc[ni][u] = 0.f;
    float mx0 = -1e30f, mx1 = -1e30f, ls0 = 0.f, ls1 = 0.f;

    const int nkv = qt + 1;
    for (int kt = 0; kt < nkv; kt++) {
        const int k0 = kt * 64;
        __syncthreads();
        const __half* kp = kb + (size_t)k0 * HD_;
        const __half* vp = vb + (size_t)k0 * HD_;
        for (int t = tid; t < 64 * 16; t += 128) {
            int r = t >> 4, c = (t & 15) * 8;
            *(uint4*)&Ks2[r * QST + c / 2] = *(const uint4*)&kp[r * HD_ + c];
        }
        for (int t = tid; t < 32 * 32; t += 128) {
            int s2 = t >> 5, c = (t & 31) * 4;
            uint2 e = *(const uint2*)&vp[(2 * s2) * HD_ + c];
            uint2 o = *(const uint2*)&vp[(2 * s2 + 1) * HD_ + c];
            uint4 u;
            u.x = __byte_perm(e.x, o.x, 0x5410);
            u.y = __byte_perm(e.x, o.x, 0x7632);
            u.z = __byte_perm(e.y, o.y, 0x5410);
            u.w = __byte_perm(e.y, o.y, 0x7632);
            *(uint4*)&Vs2[s2 * VST + c] = u;
        }
        __syncthreads();

        float sacc[8][4];
        #pragma unroll
        for (int ni = 0; ni < 8; ni++)
            #pragma unroll
            for (int u = 0; u < 4; u++) sacc[ni][u] = 0.f;

        #pragma unroll
        for (int ks = 0; ks < 8; ks++) {
            const int kw = ks * 8;
            unsigned a0 = Qs2[(m0w + gid) * QST + kw + tig];
            unsigned a1 = Qs2[(m0w + gid + 8) * QST + kw + tig];
            unsigned a2 = Qs2[(m0w + gid) * QST + kw + tig + 4];
            unsigned a3 = Qs2[(m0w + gid + 8) * QST + kw + tig + 4];
            #pragma unroll
            for (int ni = 0; ni < 8; ni++) {
                unsigned b0 = Ks2[(ni * 8 + gid) * QST + kw + tig];
                unsigned b1 = Ks2[(ni * 8 + gid) * QST + kw + tig + 4];
                MMA_F16(sacc[ni], a0, a1, a2, a3, b0, b1);
            }
        }

        if (kt == nkv - 1) {
            const int row0 = q0 + m0w + gid;
            #pragma unroll
            for (int ni = 0; ni < 8; ni++) {
                const int col = k0 + ni * 8 + tig * 2;
                if (col > row0)     sacc[ni][0] = -1e30f;
                if (col + 1 > row0) sacc[ni][1] = -1e30f;
                if (col > row0 + 8)     sacc[ni][2] = -1e30f;
                if (col + 1 > row0 + 8) sacc[ni][3] = -1e30f;
            }
        }

        float rm0 = -1e30f, rm1 = -1e30f;
        #pragma unroll
        for (int ni = 0; ni < 8; ni++) {
            rm0 = fmaxf(rm0, fmaxf(sacc[ni][0], sacc[ni][1]));
            rm1 = fmaxf(rm1, fmaxf(sacc[ni][2], sacc[ni][3]));
        }
        rm0 = fmaxf(rm0, __shfl_xor_sync(0xffffffffu, rm0, 1));
        rm0 = fmaxf(rm0, __shfl_xor_sync(0xffffffffu, rm0, 2));
        rm1 = fmaxf(rm1, __shfl_xor_sync(0xffffffffu, rm1, 1));
        rm1 = fmaxf(rm1, __shfl_xor_sync(0xffffffffu, rm1, 2));

        const float mn0 = fmaxf(mx0, rm0), mn1 = fmaxf(mx1, rm1);
        const float f0 = __expf(mx0 - mn0), f1 = __expf(mx1 - mn1);
        float rs0 = 0.f, rs1 = 0.f;
        #pragma unroll
        for (int ni = 0; ni < 8; ni++) {
            float p0 = __expf(sacc[ni][0] - mn0);
            float p1 = __expf(sacc[ni][1] - mn0);
            float p2 = __expf(sacc[ni][2] - mn1);
            float p3 = __expf(sacc[ni][3] - mn1);
            sacc[ni][0] = p0; sacc[ni][1] = p1;
            sacc[ni][2] = p2; sacc[ni][3] = p3;
            rs0 += p0 + p1; rs1 += p2 + p3;
        }
        rs0 += __shfl_xor_sync(0xffffffffu, rs0, 1);
        rs0 += __shfl_xor_sync(0xffffffffu, rs0, 2);
        rs1 += __shfl_xor_sync(0xffffffffu, rs1, 1);
        rs1 += __shfl_xor_sync(0xffffffffu, rs1, 2);
        ls0 = ls0 * f0 + rs0; ls1 = ls1 * f1 + rs1;
        mx0 = mn0; mx1 = mn1;

        #pragma unroll
        for (int ni = 0; ni < 16; ni++) {
            oacc[ni][0] *= f0; oacc[ni][1] *= f0;
            oacc[ni][2] *= f1; oacc[ni][3] *= f1;
        }

        #pragma unroll
        for (int j = 0; j < 4; j++) {
            unsigned pa0 = h2u(sacc[2 * j][0], sacc[2 * j][1]);
            unsigned pa1 = h2u(sacc[2 * j][2], sacc[2 * j][3]);
            unsigned pa2 = h2u(sacc[2 * j + 1][0], sacc[2 * j + 1][1]);
            unsigned pa3 = h2u(sacc[2 * j + 1][2], sacc[2 * j + 1][3]);
            #pragma unroll
            for (int ni = 0; ni < 16; ni++) {
                const int nc = ni * 8 + gid;
                unsigned b0 = Vs2[(8 * j + tig) * VST + nc];
                unsigned b1 = Vs2[(8 * j + 4 + tig) * VST + nc];
                MMA_F16(oacc[ni], pa0, pa1, pa2, pa3, b0, b1);
            }
        }
    }

    const float inv0 = 1.f / ls0, inv1 = 1.f / ls1;
    const int b = bh >> 4, h = bh & 15;
    const int s0 = q0 + m0w + gid;
    #pragma unroll
    for (int ni = 0; ni < 16; ni++) {
        const int col = ni * 8 + tig * 2;
        *(unsigned*)&ctx[(size_t)(b * S_ + s0) * DM_ + h * HD_ + col] =
            h2u(oacc[ni][0] * inv0, oacc[ni][1] * inv0);
        *(unsigned*)&ctx[(size_t)(b * S_ + s0 + 8) * DM_ + h * HD_ + col] =
            h2u(oacc[ni][2] * inv1, oacc[ni][3] * inv1);
    }
}

// ---------------------------------------------------------------------------
// Launch
// ---------------------------------------------------------------------------
extern "C" void kernel_launch(void* const* d_in, const int* in_sizes, int n_in,
                              void* d_out, int out_size)
{
    const float* hs = (const float*)d_in[0];
    const float* Wq = (const float*)d_in[1];
    const float* bq = (const float*)d_in[2];
    const float* Wk = (const float*)d_in[3];
    const float* bk = (const float*)d_in[4];
    const float* Wv = (const float*)d_in[5];
    const float* bv = (const float*)d_in[6];
    const float* Wo = (const float*)d_in[7];
    const float* bo = (const float*)d_in[8];
    float* out = (float*)d_out;

    __half *qd, *kd, *vd, *ctxd, *ahd;
    unsigned* wtd;
    cudaGetSymbolAddress((void**)&qd,   g_qh);
    cudaGetSymbolAddress((void**)&kd,   g_kh);
    cudaGetSymbolAddress((void**)&vd,   g_vh);
    cudaGetSymbolAddress((void**)&ctxd, g_ctxh);
    cudaGetSymbolAddress((void**)&ahd,  g_ah);
    cudaGetSymbolAddress((void**)&wtd,  g_wt);
    unsigned* wq_t = wtd + 0 * (size_t)(DM_ / 2) * DM_;
    unsigned* wk_t = wtd + 1 * (size_t)(DM_ / 2) * DM_;
    unsigned* wv_t = wtd + 2 * (size_t)(DM_ / 2) * DM_;
    unsigned* wo_t = wtd + 3 * (size_t)(DM_ / 2) * DM_;

    const int gemm_smem = 3 * STAGEB;                       // 107520
    const int attn_smem = (2 * QWORDS + 32 * VST) * (int)sizeof(unsigned);
    static int smem_set = 0;
    if (!smem_set) {
        cudaFuncSetAttribute(hgemm2_kernel,
                             cudaFuncAttributeMaxDynamicSharedMemorySize,
                             gemm_smem);
        cudaFuncSetAttribute(attn_h_kernel,
                             cudaFuncAttributeMaxDynamicSharedMemorySize,
                             attn_smem);
        smem_set = 1;
    }

    rope_table_kernel<<<(S_ * (HD_ / 2) + 255) / 256, 256>>>();

    const int na8 = BS_ * DM_ / 8;
    const int nw  = (GK / 2) * (GN / 4);
    cvt_a_kernel<<<(na8 + 255) / 256, 256>>>(hs, ahd, na8);
    dim3 wgrid((nw + 255) / 256, 1, 4);
    cvt_w_kernel<<<wgrid, 256>>>(Wq, Wk, Wv, Wo, wtd);

    dim3 qkvgrid(GN / 128, 4096 / 128, 3);
    hgemm2_kernel<<<qkvgrid, 256, gemm_smem>>>(
        ahd, wq_t, wk_t, wv_t, bq, bk, bv, qd, kd, vd, -1);

    dim3 agrid(S_ / 64, B_ * NH_);
    attn_h_kernel<<<agrid, 128, attn_smem>>>(qd, kd, vd, ctxd);

    dim3 ogrid(GN / 128, 4096 / 128, 1);
    hgemm2_kernel<<<ogrid, 256, gemm_smem>>>(
        ctxd, wo_t, nullptr, nullptr, bo, nullptr, nullptr, out, nullptr,
        nullptr, 2);
}

// round 14
// speedup vs baseline: 1.1187x; 1.0514x over previous
#include <cuda_runtime.h>
#include <cuda_fp16.h>
#include <math.h>
#include <stdint.h>

// Problem constants
#define B_  2
#define S_  2048
#define DM_ 2048
#define NH_ 16
#define HD_ 128
#define BS_ (B_ * S_)
#define SCALE_ 0.08838834764831845f   // 1/sqrt(128)
#define GK 2048
#define GN 2048

// ---------------------------------------------------------------------------
// Scratch
// ---------------------------------------------------------------------------
__device__ __half g_qh[B_ * NH_ * S_ * HD_];
__device__ __half g_kh[B_ * NH_ * S_ * HD_];
__device__ __half g_vh[B_ * NH_ * S_ * HD_];
__device__ __half g_ctxh[BS_ * DM_];
__device__ __half g_ah[BS_ * DM_];
__device__ unsigned g_wt[4][(DM_ / 2) * DM_];  // k-pair-interleaved half2 W
__device__ float g_cos[S_ * (HD_ / 2)];
__device__ float g_sin[S_ * (HD_ / 2)];

// ---------------------------------------------------------------------------
// RoPE table (double precision)
// ---------------------------------------------------------------------------
__global__ void rope_table_kernel() {
    int idx = blockIdx.x * blockDim.x + threadIdx.x;
    if (idx >= S_ * (HD_ / 2)) return;
    int s = idx / (HD_ / 2);
    int i = idx % (HD_ / 2);
    double inv_freq = exp(-((double)(2 * i) / (double)HD_) * log(10000.0));
    double ang = (double)s * inv_freq;
    g_cos[idx] = (float)cos(ang);
    g_sin[idx] = (float)sin(ang);
}

__device__ __forceinline__ unsigned h2u(float lo, float hi) {
    __half2 h = __floats2half2_rn(lo, hi);
    return *(unsigned*)&h;
}

// hs f32 -> half (8 elems/thread)
__global__ void cvt_a_kernel(const float* __restrict__ in,
                             __half* __restrict__ out, int n8) {
    int i = blockIdx.x * blockDim.x + threadIdx.x;
    if (i >= n8) return;
    float4 f0 = ((const float4*)in)[2 * i];
    float4 f1 = ((const float4*)in)[2 * i + 1];
    uint4 u;
    u.x = h2u(f0.x, f0.y); u.y = h2u(f0.z, f0.w);
    u.z = h2u(f1.x, f1.y); u.w = h2u(f1.z, f1.w);
    ((uint4*)out)[i] = u;
}

// W[k][n] f32 -> Wt[k2][n] = half2(W[2k2][n], W[2k2+1][n]); z selects weight
__global__ void cvt_w_kernel(const float* __restrict__ W0,
                             const float* __restrict__ W1,
                             const float* __restrict__ W2,
                             const float* __restrict__ W3,
                             unsigned* __restrict__ Wt) {
    int idx = blockIdx.x * blockDim.x + threadIdx.x;
    if (idx >= (GK / 2) * (GN / 4)) return;
    const int z = blockIdx.z;
    const float* W = (z == 0) ? W0 : (z == 1) ? W1 : (z == 2) ? W2 : W3;
    unsigned* Wz = Wt + (size_t)z * (GK / 2) * GN;
    int k2 = idx / (GN / 4);
    int n  = (idx % (GN / 4)) * 4;
    float4 f0 = *(const float4*)(W + (size_t)(2 * k2) * GN + n);
    float4 f1 = *(const float4*)(W + (size_t)(2 * k2 + 1) * GN + n);
    uint4 u;
    u.x = h2u(f0.x, f1.x); u.y = h2u(f0.y, f1.y);
    u.z = h2u(f0.z, f1.z); u.w = h2u(f0.w, f1.w);
    *(uint4*)(Wz + (size_t)k2 * GN + n) = u;
}

__device__ __forceinline__ uint32_t smem_u32(const void* p) {
    uint32_t a;
    asm("{ .reg .u64 t; cvta.to.shared.u64 t, %1; cvt.u32.u64 %0, t; }"
        : "=r"(a) : "l"(p));
    return a;
}

#define CP_ASYNC16(dst, src)                                                  \
    asm volatile("cp.async.cg.shared.global [%0], [%1], 16;"                  \
                 :: "r"(dst), "l"(src) : "memory")

#define MMA_F16(Cc, a0, a1, a2, a3, b0, b1)                                   \
    asm volatile(                                                             \
        "mma.sync.aligned.m16n8k16.row.col.f32.f16.f16.f32 "                  \
        "{%0,%1,%2,%3}, {%4,%5,%6,%7}, {%8,%9}, {%0,%1,%2,%3};"               \
        : "+f"((Cc)[0]), "+f"((Cc)[1]), "+f"((Cc)[2]), "+f"((Cc)[3])          \
        : "r"(a0), "r"(a1), "r"(a2), "r"(a3), "r"(b0), "r"(b1))

// ---------------------------------------------------------------------------
// FP16 GEMM (exact R9 config): 128x128 CTA, 256 thr, 8 warps of 64x32,
// k16 MMA, BK=32, cp.async 3-stage pipeline.
// As2 [m][k2] stride 20 words; Bs2 [k2][n] stride 136 words.
// mode 0: rope+scale -> half scatter (Q)  mode 3: rope -> half scatter (K)
// mode 1: half scatter (V)                mode 2: float row-major (O proj)
// mode0 < 0: derive from blockIdx.z.
// ---------------------------------------------------------------------------
#define ASTRIDE 20
#define BSTRIDE 136
#define ABYTES  (128 * ASTRIDE * 4)           // 10240
#define STAGEB  (ABYTES + 16 * BSTRIDE * 4)   // 18944
#define NKB (GK / 32)                          // 64

__global__ __launch_bounds__(256) void hgemm2_kernel(
    const __half* __restrict__ Ah,
    const unsigned* __restrict__ Wt0, const unsigned* __restrict__ Wt1,
    const unsigned* __restrict__ Wt2,
    const float* __restrict__ b0p, const float* __restrict__ b1p,
    const float* __restrict__ b2p,
    void* __restrict__ C0, void* __restrict__ C1, void* __restrict__ C2,
    int mode0)
{
    extern __shared__ unsigned char smraw[];

    const unsigned* Wt; const float* bias; void* C; int mode;
    if (mode0 >= 0) { Wt = Wt0; bias = b0p; C = C0; mode = mode0; }
    else {
        const int z = blockIdx.z;
        Wt   = (z == 0) ? Wt0 : (z == 1) ? Wt1 : Wt2;
        bias = (z == 0) ? b0p : (z == 1) ? b1p : b2p;
        C    = (z == 0) ? C0 : (z == 1) ? C1 : C2;
        mode = (z == 0) ? 0 : (z == 1) ? 3 : 1;
    }

    const int tid  = threadIdx.x;
    const int lane = tid & 31, wid = tid >> 5;
    const int warpM = wid >> 2, warpN = wid & 3;
    const int gid = lane >> 2, tig = lane & 3;
    const int m0 = blockIdx.y * 128, n0 = blockIdx.x * 128;

    const uint32_t sb = smem_u32(smraw);

    const int arow = tid >> 1, ac = tid & 1;
    const __half* asrc0 = Ah + (size_t)(m0 + arow) * GK + ac * 16;
    const int brow = tid >> 4, bc = tid & 15;
    const unsigned* bsrc0 = Wt + (size_t)brow * GN + n0 + bc * 8;

    auto issue = [&](int ib) {
        const uint32_t base = sb + (ib % 3) * STAGEB;
        const __half* as = asrc0 + ib * 32;
        CP_ASYNC16(base + arow * 80 + ac * 32, as);
        CP_ASYNC16(base + arow * 80 + ac * 32 + 16, as + 8);
        const unsigned* bs = bsrc0 + (size_t)(ib * 16) * GN;
        CP_ASYNC16(base + ABYTES + brow * 544 + bc * 32, bs);
        CP_ASYNC16(base + ABYTES + brow * 544 + bc * 32 + 16, bs + 4);
        asm volatile("cp.async.commit_group;" ::: "memory");
    };
    issue(0);
    issue(1);

    float acc[4][4][4];
    #pragma unroll
    for (int mi = 0; mi < 4; mi++)
        #pragma unroll
        for (int ni = 0; ni < 4; ni++)
            #pragma unroll
            for (int u = 0; u < 4; u++) acc[mi][ni][u] = 0.f;

    for (int ib = 0; ib < NKB; ib++) {
        if (ib + 2 < NKB)
            asm volatile("cp.async.wait_group 1;" ::: "memory");
        else
            asm volatile("cp.async.wait_group 0;" ::: "memory");
        __syncthreads();
        if (ib + 2 < NKB) issue(ib + 2);

        const unsigned* As2 = (const unsigned*)(smraw + (ib % 3) * STAGEB);
        const unsigned* Bs2 = (const unsigned*)(smraw + (ib % 3) * STAGEB + ABYTES);

        #pragma unroll
        for (int kk2 = 0; kk2 < 16; kk2 += 8) {
            unsigned af[4][4], bf[4][2];
            #pragma unroll
            for (int mi = 0; mi < 4; mi++) {
                const int mr = warpM * 64 + mi * 16 + gid;
                af[mi][0] = As2[mr * ASTRIDE + kk2 + tig];
                af[mi][1] = As2[(mr + 8) * ASTRIDE + kk2 + tig];
                af[mi][2] = As2[mr * ASTRIDE + kk2 + tig + 4];
                af[mi][3] = As2[(mr + 8) * ASTRIDE + kk2 + tig + 4];
            }
            #pragma unroll
            for (int ni = 0; ni < 4; ni++) {
                const int nc = warpN * 32 + ni * 8 + gid;
                bf[ni][0] = Bs2[(kk2 + tig) * BSTRIDE + nc];
                bf[ni][1] = Bs2[(kk2 + tig + 4) * BSTRIDE + nc];
            }
            #pragma unroll
            for (int mi = 0; mi < 4; mi++)
                #pragma unroll
                for (int ni = 0; ni < 4; ni++)
                    MMA_F16(acc[mi][ni], af[mi][0], af[mi][1], af[mi][2],
                            af[mi][3], bf[ni][0], bf[ni][1]);
        }
        __syncthreads();
    }

    // Epilogue
    #pragma unroll
    for (int ni = 0; ni < 4; ni++) {
        const int c = n0 + warpN * 32 + ni * 8 + tig * 2;
        const float bv0 = bias[c], bv1 = bias[c + 1];
        #pragma unroll
        for (int mi = 0; mi < 4; mi++) {
            #pragma unroll
            for (int half_ = 0; half_ < 2; half_++) {
                const int r = m0 + warpM * 64 + mi * 16 + gid + half_ * 8;
                float v0 = acc[mi][ni][half_ * 2 + 0] + bv0;
                float v1 = acc[mi][ni][half_ * 2 + 1] + bv1;
                const int bb = r >> 11;
                const int s  = r & (S_ - 1);
                if (mode == 0 || mode == 3) {
                    const int pi = (c & (HD_ - 1)) >> 1;
                    const float cs = g_cos[s * (HD_ / 2) + pi];
                    const float sn = g_sin[s * (HD_ / 2) + pi];
                    const float e = v0, o = v1;
                    v0 = e * cs - o * sn;
                    v1 = o * cs + e * sn;
                    if (mode == 0) { v0 *= SCALE_; v1 *= SCALE_; }
                }
                if (mode != 2) {
                    const int h = (c >> 7) & (NH_ - 1);
                    const int d = c & (HD_ - 1);
                    __half* dst = (__half*)C +
                        (size_t)((bb * NH_ + h) * S_ + s) * HD_ + d;
                    *(unsigned*)dst = h2u(v0, v1);
                } else {
                    float2 val; val.x = v0; val.y = v1;
                    *(float2*)((float*)C + (size_t)r * GN + c) = val;
                }
            }
        }
    }
}

// ---------------------------------------------------------------------------
// Flash attention (causal), fp16 m16n8k16, half I/O.
// BM=128 (256 thr, 8 warps x 16 q-rows), KV tiles of 64.
// Per-warp math identical to R9; K/V loads amortized over 2x the MMAs.
// ---------------------------------------------------------------------------
#define QST 68
#define VST 136
#define QROWS 128
#define QWORDSQ (QROWS * QST)   // 8704
#define KWORDS  (64 * QST)      // 4352

__global__ __launch_bounds__(256) void attn_h_kernel(
    const __half* __restrict__ q, const __half* __restrict__ k,
    const __half* __restrict__ v, __half* __restrict__ ctx)
{
    extern __shared__ unsigned smu[];
    unsigned* Qs2 = smu;                    // 128*68
    unsigned* Ks2 = Qs2 + QWORDSQ;          // 64*68
    unsigned* Vs2 = Ks2 + KWORDS;           // 32*136

    const int tid  = threadIdx.x;
    const int lane = tid & 31, wid = tid >> 5;
    const int gid = lane >> 2, tig = lane & 3;
    const int bh = blockIdx.y;
    const int qt = gridDim.x - 1 - blockIdx.x;   // heavy tiles first
    const int q0 = qt * QROWS;
    const int m0w = wid * 16;

    const __half* qp = q + ((size_t)bh * S_ + q0) * HD_;
    const __half* kb = k + (size_t)bh * S_ * HD_;
    const __half* vb = v + (size_t)bh * S_ * HD_;

    for (int t = tid; t < QROWS * 16; t += 256) {
        int r = t >> 4, c = (t & 15) * 8;
        *(uint4*)&Qs2[r * QST + c / 2] = *(const uint4*)&qp[r * HD_ + c];
    }

    float oacc[16][4];
    #pragma unroll
    for (int ni = 0; ni < 16; ni++)
        #pragma unroll
        for (int u = 0; u < 4; u++) oacc[ni][u] = 0.f;
    float mx0 = -1e30f, mx1 = -1e30f, ls0 = 0.f, ls1 = 0.f;

    const int nkv = 2 * qt + 2;
    for (int kt = 0; kt < nkv; kt++) {
        const int k0 = kt * 64;
        __syncthreads();
        const __half* kp = kb + (size_t)k0 * HD_;
        const __half* vp = vb + (size_t)k0 * HD_;
        for (int t = tid; t < 64 * 16; t += 256) {
            int r = t >> 4, c = (t & 15) * 8;
            *(uint4*)&Ks2[r * QST + c / 2] = *(const uint4*)&kp[r * HD_ + c];
        }
        for (int t = tid; t < 32 * 32; t += 256) {
            int s2 = t >> 5, c = (t & 31) * 4;
            uint2 e = *(const uint2*)&vp[(2 * s2) * HD_ + c];
            uint2 o = *(const uint2*)&vp[(2 * s2 + 1) * HD_ + c];
            uint4 u;
            u.x = __byte_perm(e.x, o.x, 0x5410);
            u.y = __byte_perm(e.x, o.x, 0x7632);
            u.z = __byte_perm(e.y, o.y, 0x5410);
            u.w = __byte_perm(e.y, o.y, 0x7632);
            *(uint4*)&Vs2[s2 * VST + c] = u;
        }
        __syncthreads();

        float sacc[8][4];
        #pragma unroll
        for (int ni = 0; ni < 8; ni++)
            #pragma unroll
            for (int u = 0; u < 4; u++) sacc[ni][u] = 0.f;

        #pragma unroll
        for (int ks = 0; ks < 8; ks++) {
            const int kw = ks * 8;
            unsigned a0 = Qs2[(m0w + gid) * QST + kw + tig];
            unsigned a1 = Qs2[(m0w + gid + 8) * QST + kw + tig];
            unsigned a2 = Qs2[(m0w + gid) * QST + kw + tig + 4];
            unsigned a3 = Qs2[(m0w + gid + 8) * QST + kw + tig + 4];
            #pragma unroll
            for (int ni = 0; ni < 8; ni++) {
                unsigned b0 = Ks2[(ni * 8 + gid) * QST + kw + tig];
                unsigned b1 = Ks2[(ni * 8 + gid) * QST + kw + tig + 4];
                MMA_F16(sacc[ni], a0, a1, a2, a3, b0, b1);
            }
        }

        // causal mask: only the last two KV tiles can intersect the diagonal
        if (kt >= nkv - 2) {
            const int row0 = q0 + m0w + gid;
            #pragma unroll
            for (int ni = 0; ni < 8; ni++) {
                const int col = k0 + ni * 8 + tig * 2;
                if (col > row0)     sacc[ni][0] = -1e30f;
                if (col + 1 > row0) sacc[ni][1] = -1e30f;
                if (col > row0 + 8)     sacc[ni][2] = -1e30f;
                if (col + 1 > row0 + 8) sacc[ni][3] = -1e30f;
            }
        }

        float rm0 = -1e30f, rm1 = -1e30f;
        #pragma unroll
        for (int ni = 0; ni < 8; ni++) {
            rm0 = fmaxf(rm0, fmaxf(sacc[ni][0], sacc[ni][1]));
            rm1 = fmaxf(rm1, fmaxf(sacc[ni][2], sacc[ni][3]));
        }
        rm0 = fmaxf(rm0, __shfl_xor_sync(0xffffffffu, rm0, 1));
        rm0 = fmaxf(rm0, __shfl_xor_sync(0xffffffffu, rm0, 2));
        rm1 = fmaxf(rm1, __shfl_xor_sync(0xffffffffu, rm1, 1));
        rm1 = fmaxf(rm1, __shfl_xor_sync(0xffffffffu, rm1, 2));

        const float mn0 = fmaxf(mx0, rm0), mn1 = fmaxf(mx1, rm1);
        const float f0 = __expf(mx0 - mn0), f1 = __expf(mx1 - mn1);
        float rs0 = 0.f, rs1 = 0.f;
        #pragma unroll
        for (int ni = 0; ni < 8; ni++) {
            float p0 = __expf(sacc[ni][0] - mn0);
            float p1 = __expf(sacc[ni][1] - mn0);
            float p2 = __expf(sacc[ni][2] - mn1);
            float p3 = __expf(sacc[ni][3] - mn1);
            sacc[ni][0] = p0; sacc[ni][1] = p1;
            sacc[ni][2] = p2; sacc[ni][3] = p3;
            rs0 += p0 + p1; rs1 += p2 + p3;
        }
        rs0 += __shfl_xor_sync(0xffffffffu, rs0, 1);
        rs0 += __shfl_xor_sync(0xffffffffu, rs0, 2);
        rs1 += __shfl_xor_sync(0xffffffffu, rs1, 1);
        rs1 += __shfl_xor_sync(0xffffffffu, rs1, 2);
        ls0 = ls0 * f0 + rs0; ls1 = ls1 * f1 + rs1;
        mx0 = mn0; mx1 = mn1;

        #pragma unroll
        for (int ni = 0; ni < 16; ni++) {
            oacc[ni][0] *= f0; oacc[ni][1] *= f0;
            oacc[ni][2] *= f1; oacc[ni][3] *= f1;
        }

        #pragma unroll
        for (int j = 0; j < 4; j++) {
            unsigned pa0 = h2u(sacc[2 * j][0], sacc[2 * j][1]);
            unsigned pa1 = h2u(sacc[2 * j][2], sacc[2 * j][3]);
            unsigned pa2 = h2u(sacc[2 * j + 1][0], sacc[2 * j + 1][1]);
            unsigned pa3 = h2u(sacc[2 * j + 1][2], sacc[2 * j + 1][3]);
            #pragma unroll
            for (int ni = 0; ni < 16; ni++) {
                const int nc = ni * 8 + gid;
                unsigned b0 = Vs2[(8 * j + tig) * VST + nc];
                unsigned b1 = Vs2[(8 * j + 4 + tig) * VST + nc];
                MMA_F16(oacc[ni], pa0, pa1, pa2, pa3, b0, b1);
            }
        }
    }

    const float inv0 = 1.f / ls0, inv1 = 1.f / ls1;
    const int b = bh >> 4, h = bh & 15;
    const int s0 = q0 + m0w + gid;
    #pragma unroll
    for (int ni = 0; ni < 16; ni++) {
        const int col = ni * 8 + tig * 2;
        *(unsigned*)&ctx[(size_t)(b * S_ + s0) * DM_ + h * HD_ + col] =
            h2u(oacc[ni][0] * inv0, oacc[ni][1] * inv0);
        *(unsigned*)&ctx[(size_t)(b * S_ + s0 + 8) * DM_ + h * HD_ + col] =
            h2u(oacc[ni][2] * inv1, oacc[ni][3] * inv1);
    }
}

// ---------------------------------------------------------------------------
// Launch
// ---------------------------------------------------------------------------
extern "C" void kernel_launch(void* const* d_in, const int* in_sizes, int n_in,
                              void* d_out, int out_size)
{
    const float* hs = (const float*)d_in[0];
    const float* Wq = (const float*)d_in[1];
    const float* bq = (const float*)d_in[2];
    const float* Wk = (const float*)d_in[3];
    const float* bk = (const float*)d_in[4];
    const float* Wv = (const float*)d_in[5];
    const float* bv = (const float*)d_in[6];
    const float* Wo = (const float*)d_in[7];
    const float* bo = (const float*)d_in[8];
    float* out = (float*)d_out;

    __half *qd, *kd, *vd, *ctxd, *ahd;
    unsigned* wtd;
    cudaGetSymbolAddress((void**)&qd,   g_qh);
    cudaGetSymbolAddress((void**)&kd,   g_kh);
    cudaGetSymbolAddress((void**)&vd,   g_vh);
    cudaGetSymbolAddress((void**)&ctxd, g_ctxh);
    cudaGetSymbolAddress((void**)&ahd,  g_ah);
    cudaGetSymbolAddress((void**)&wtd,  g_wt);
    unsigned* wq_t = wtd + 0 * (size_t)(DM_ / 2) * DM_;
    unsigned* wk_t = wtd + 1 * (size_t)(DM_ / 2) * DM_;
    unsigned* wv_t = wtd + 2 * (size_t)(DM_ / 2) * DM_;
    unsigned* wo_t = wtd + 3 * (size_t)(DM_ / 2) * DM_;

    const int gemm_smem = 3 * STAGEB;                       // 56832
    const int attn_smem = (QWORDSQ + KWORDS + 32 * VST) * (int)sizeof(unsigned);
    static int smem_set = 0;
    if (!smem_set) {
        cudaFuncSetAttribute(hgemm2_kernel,
                             cudaFuncAttributeMaxDynamicSharedMemorySize,
                             gemm_smem);
        cudaFuncSetAttribute(attn_h_kernel,
                             cudaFuncAttributeMaxDynamicSharedMemorySize,
                             attn_smem);
        smem_set = 1;
    }

    rope_table_kernel<<<(S_ * (HD_ / 2) + 255) / 256, 256>>>();

    const int na8 = BS_ * DM_ / 8;
    const int nw  = (GK / 2) * (GN / 4);
    cvt_a_kernel<<<(na8 + 255) / 256, 256>>>(hs, ahd, na8);
    dim3 wgrid((nw + 255) / 256, 1, 4);
    cvt_w_kernel<<<wgrid, 256>>>(Wq, Wk, Wv, Wo, wtd);

    dim3 qkvgrid(GN / 128, 4096 / 128, 3);
    hgemm2_kernel<<<qkvgrid, 256, gemm_smem>>>(
        ahd, wq_t, wk_t, wv_t, bq, bk, bv, qd, kd, vd, -1);

    dim3 agrid(S_ / QROWS, B_ * NH_);
    attn_h_kernel<<<agrid, 256, attn_smem>>>(qd, kd, vd, ctxd);

    dim3 ogrid(GN / 128, 4096 / 128, 1);
    hgemm2_kernel<<<ogrid, 256, gemm_smem>>>(
        ctxd, wo_t, nullptr, nullptr, bo, nullptr, nullptr, out, nullptr,
        nullptr, 2);
}

// round 15
// speedup vs baseline: 1.1617x; 1.0385x over previous
#include <cuda_runtime.h>
#include <cuda_fp16.h>
#include <math.h>
#include <stdint.h>

// Problem constants
#define B_  2
#define S_  2048
#define DM_ 2048
#define NH_ 16
#define HD_ 128
#define BS_ (B_ * S_)
#define SCALE_ 0.08838834764831845f   // 1/sqrt(128)
#define GK 2048
#define GN 2048

// ---------------------------------------------------------------------------
// Scratch
// ---------------------------------------------------------------------------
__device__ __half g_qh[B_ * NH_ * S_ * HD_];
__device__ __half g_kh[B_ * NH_ * S_ * HD_];
__device__ __half g_vh[B_ * NH_ * S_ * HD_];
__device__ __half g_ctxh[BS_ * DM_];
__device__ __half g_ah[BS_ * DM_];
__device__ unsigned g_wt[4][(DM_ / 2) * DM_];  // k-pair-interleaved half2 W
__device__ float g_cos[S_ * (HD_ / 2)];
__device__ float g_sin[S_ * (HD_ / 2)];

// ---------------------------------------------------------------------------
// RoPE table (double precision)
// ---------------------------------------------------------------------------
__global__ void rope_table_kernel() {
    int idx = blockIdx.x * blockDim.x + threadIdx.x;
    if (idx >= S_ * (HD_ / 2)) return;
    int s = idx / (HD_ / 2);
    int i = idx % (HD_ / 2);
    double inv_freq = exp(-((double)(2 * i) / (double)HD_) * log(10000.0));
    double ang = (double)s * inv_freq;
    g_cos[idx] = (float)cos(ang);
    g_sin[idx] = (float)sin(ang);
}

__device__ __forceinline__ unsigned h2u(float lo, float hi) {
    __half2 h = __floats2half2_rn(lo, hi);
    return *(unsigned*)&h;
}

// hs f32 -> half (8 elems/thread)
__global__ void cvt_a_kernel(const float* __restrict__ in,
                             __half* __restrict__ out, int n8) {
    int i = blockIdx.x * blockDim.x + threadIdx.x;
    if (i >= n8) return;
    float4 f0 = ((const float4*)in)[2 * i];
    float4 f1 = ((const float4*)in)[2 * i + 1];
    uint4 u;
    u.x = h2u(f0.x, f0.y); u.y = h2u(f0.z, f0.w);
    u.z = h2u(f1.x, f1.y); u.w = h2u(f1.z, f1.w);
    ((uint4*)out)[i] = u;
}

// W[k][n] f32 -> Wt[k2][n] = half2(W[2k2][n], W[2k2+1][n]); z selects weight
__global__ void cvt_w_kernel(const float* __restrict__ W0,
                             const float* __restrict__ W1,
                             const float* __restrict__ W2,
                             const float* __restrict__ W3,
                             unsigned* __restrict__ Wt) {
    int idx = blockIdx.x * blockDim.x + threadIdx.x;
    if (idx >= (GK / 2) * (GN / 4)) return;
    const int z = blockIdx.z;
    const float* W = (z == 0) ? W0 : (z == 1) ? W1 : (z == 2) ? W2 : W3;
    unsigned* Wz = Wt + (size_t)z * (GK / 2) * GN;
    int k2 = idx / (GN / 4);
    int n  = (idx % (GN / 4)) * 4;
    float4 f0 = *(const float4*)(W + (size_t)(2 * k2) * GN + n);
    float4 f1 = *(const float4*)(W + (size_t)(2 * k2 + 1) * GN + n);
    uint4 u;
    u.x = h2u(f0.x, f1.x); u.y = h2u(f0.y, f1.y);
    u.z = h2u(f0.z, f1.z); u.w = h2u(f0.w, f1.w);
    *(uint4*)(Wz + (size_t)k2 * GN + n) = u;
}

__device__ __forceinline__ uint32_t smem_u32(const void* p) {
    uint32_t a;
    asm("{ .reg .u64 t; cvta.to.shared.u64 t, %1; cvt.u32.u64 %0, t; }"
        : "=r"(a) : "l"(p));
    return a;
}

#define CP_ASYNC16(dst, src)                                                  \
    asm volatile("cp.async.cg.shared.global [%0], [%1], 16;"                  \
                 :: "r"(dst), "l"(src) : "memory")

#define MMA_F16(Cc, a0, a1, a2, a3, b0, b1)                                   \
    asm volatile(                                                             \
        "mma.sync.aligned.m16n8k16.row.col.f32.f16.f16.f32 "                  \
        "{%0,%1,%2,%3}, {%4,%5,%6,%7}, {%8,%9}, {%0,%1,%2,%3};"               \
        : "+f"((Cc)[0]), "+f"((Cc)[1]), "+f"((Cc)[2]), "+f"((Cc)[3])          \
        : "r"(a0), "r"(a1), "r"(a2), "r"(a3), "r"(b0), "r"(b1))

#define LDSM_X4(r0, r1, r2, r3, addr)                                         \
    asm volatile("ldmatrix.sync.aligned.m8n8.x4.shared.b16 "                  \
                 "{%0,%1,%2,%3}, [%4];"                                       \
                 : "=r"(r0), "=r"(r1), "=r"(r2), "=r"(r3) : "r"(addr))

// ---------------------------------------------------------------------------
// FP16 GEMM (R9 config + ldmatrix A-fragments): 128x128 CTA, 256 thr,
// 8 warps of 64x32, k16 MMA, BK=32, cp.async 3-stage pipeline.
// As2 [m][k2] stride 20 words; Bs2 [k2][n] stride 136 words.
// A fragments via LDSM.x4 (1 instr replaces 4 LDS.32); B via LDS.32.
// mode 0: rope+scale -> half scatter (Q)  mode 3: rope -> half scatter (K)
// mode 1: half scatter (V)                mode 2: float row-major (O proj)
// mode0 < 0: derive from blockIdx.z.
// ---------------------------------------------------------------------------
#define ASTRIDE 20
#define BSTRIDE 136
#define ABYTES  (128 * ASTRIDE * 4)           // 10240
#define STAGEB  (ABYTES + 16 * BSTRIDE * 4)   // 18944
#define NKB (GK / 32)                          // 64

__global__ __launch_bounds__(256) void hgemm2_kernel(
    const __half* __restrict__ Ah,
    const unsigned* __restrict__ Wt0, const unsigned* __restrict__ Wt1,
    const unsigned* __restrict__ Wt2,
    const float* __restrict__ b0p, const float* __restrict__ b1p,
    const float* __restrict__ b2p,
    void* __restrict__ C0, void* __restrict__ C1, void* __restrict__ C2,
    int mode0)
{
    extern __shared__ unsigned char smraw[];

    const unsigned* Wt; const float* bias; void* C; int mode;
    if (mode0 >= 0) { Wt = Wt0; bias = b0p; C = C0; mode = mode0; }
    else {
        const int z = blockIdx.z;
        Wt   = (z == 0) ? Wt0 : (z == 1) ? Wt1 : Wt2;
        bias = (z == 0) ? b0p : (z == 1) ? b1p : b2p;
        C    = (z == 0) ? C0 : (z == 1) ? C1 : C2;
        mode = (z == 0) ? 0 : (z == 1) ? 3 : 1;
    }

    const int tid  = threadIdx.x;
    const int lane = tid & 31, wid = tid >> 5;
    const int warpM = wid >> 2, warpN = wid & 3;
    const int gid = lane >> 2, tig = lane & 3;
    const int m0 = blockIdx.y * 128, n0 = blockIdx.x * 128;

    const uint32_t sb = smem_u32(smraw);

    const int arow = tid >> 1, ac = tid & 1;
    const __half* asrc0 = Ah + (size_t)(m0 + arow) * GK + ac * 16;
    const int brow = tid >> 4, bc = tid & 15;
    const unsigned* bsrc0 = Wt + (size_t)brow * GN + n0 + bc * 8;

    // LDSM per-lane address component (bytes):
    //   row = warpM*64 + mi*16 + (lane & 15), koff words = kk2 + (lane>>4)*4
    const uint32_t ldsm_lane_off =
        (uint32_t)(((warpM * 64 + (lane & 15)) * ASTRIDE + (lane >> 4) * 4) * 4);

    auto issue = [&](int ib) {
        const uint32_t base = sb + (ib % 3) * STAGEB;
        const __half* as = asrc0 + ib * 32;
        CP_ASYNC16(base + arow * 80 + ac * 32, as);
        CP_ASYNC16(base + arow * 80 + ac * 32 + 16, as + 8);
        const unsigned* bs = bsrc0 + (size_t)(ib * 16) * GN;
        CP_ASYNC16(base + ABYTES + brow * 544 + bc * 32, bs);
        CP_ASYNC16(base + ABYTES + brow * 544 + bc * 32 + 16, bs + 4);
        asm volatile("cp.async.commit_group;" ::: "memory");
    };
    issue(0);
    issue(1);

    float acc[4][4][4];
    #pragma unroll
    for (int mi = 0; mi < 4; mi++)
        #pragma unroll
        for (int ni = 0; ni < 4; ni++)
            #pragma unroll
            for (int u = 0; u < 4; u++) acc[mi][ni][u] = 0.f;

    for (int ib = 0; ib < NKB; ib++) {
        if (ib + 2 < NKB)
            asm volatile("cp.async.wait_group 1;" ::: "memory");
        else
            asm volatile("cp.async.wait_group 0;" ::: "memory");
        __syncthreads();
        if (ib + 2 < NKB) issue(ib + 2);

        const uint32_t a_base = sb + (ib % 3) * STAGEB + ldsm_lane_off;
        const unsigned* Bs2 = (const unsigned*)(smraw + (ib % 3) * STAGEB + ABYTES);

        #pragma unroll
        for (int kk2 = 0; kk2 < 16; kk2 += 8) {
            unsigned af[4][4], bf[4][2];
            #pragma unroll
            for (int mi = 0; mi < 4; mi++) {
                const uint32_t aaddr = a_base + (mi * 16 * ASTRIDE + kk2) * 4;
                LDSM_X4(af[mi][0], af[mi][1], af[mi][2], af[mi][3], aaddr);
            }
            #pragma unroll
            for (int ni = 0; ni < 4; ni++) {
                const int nc = warpN * 32 + ni * 8 + gid;
                bf[ni][0] = Bs2[(kk2 + tig) * BSTRIDE + nc];
                bf[ni][1] = Bs2[(kk2 + tig + 4) * BSTRIDE + nc];
            }
            #pragma unroll
            for (int mi = 0; mi < 4; mi++)
                #pragma unroll
                for (int ni = 0; ni < 4; ni++)
                    MMA_F16(acc[mi][ni], af[mi][0], af[mi][1], af[mi][2],
                            af[mi][3], bf[ni][0], bf[ni][1]);
        }
        __syncthreads();
    }

    // Epilogue
    #pragma unroll
    for (int ni = 0; ni < 4; ni++) {
        const int c = n0 + warpN * 32 + ni * 8 + tig * 2;
        const float bv0 = bias[c], bv1 = bias[c + 1];
        #pragma unroll
        for (int mi = 0; mi < 4; mi++) {
            #pragma unroll
            for (int half_ = 0; half_ < 2; half_++) {
                const int r = m0 + warpM * 64 + mi * 16 + gid + half_ * 8;
                float v0 = acc[mi][ni][half_ * 2 + 0] + bv0;
                float v1 = acc[mi][ni][half_ * 2 + 1] + bv1;
                const int bb = r >> 11;
                const int s  = r & (S_ - 1);
                if (mode == 0 || mode == 3) {
                    const int pi = (c & (HD_ - 1)) >> 1;
                    const float cs = g_cos[s * (HD_ / 2) + pi];
                    const float sn = g_sin[s * (HD_ / 2) + pi];
                    const float e = v0, o = v1;
                    v0 = e * cs - o * sn;
                    v1 = o * cs + e * sn;
                    if (mode == 0) { v0 *= SCALE_; v1 *= SCALE_; }
                }
                if (mode != 2) {
                    const int h = (c >> 7) & (NH_ - 1);
                    const int d = c & (HD_ - 1);
                    __half* dst = (__half*)C +
                        (size_t)((bb * NH_ + h) * S_ + s) * HD_ + d;
                    *(unsigned*)dst = h2u(v0, v1);
                } else {
                    float2 val; val.x = v0; val.y = v1;
                    *(float2*)((float*)C + (size_t)r * GN + c) = val;
                }
            }
        }
    }
}

// ---------------------------------------------------------------------------
// Flash attention (causal), fp16 m16n8k16, half I/O (R9-exact, BM=64).
// ---------------------------------------------------------------------------
#define QST 68
#define VST 136
#define QWORDS (64 * QST)

__global__ __launch_bounds__(128) void attn_h_kernel(
    const __half* __restrict__ q, const __half* __restrict__ k,
    const __half* __restrict__ v, __half* __restrict__ ctx)
{
    extern __shared__ unsigned smu[];
    unsigned* Qs2 = smu;
    unsigned* Ks2 = Qs2 + QWORDS;
    unsigned* Vs2 = Ks2 + QWORDS;

    const int tid  = threadIdx.x;
    const int lane = tid & 31, wid = tid >> 5;
    const int gid = lane >> 2, tig = lane & 3;
    const int bh = blockIdx.y;
    const int qt = gridDim.x - 1 - blockIdx.x;
    const int q0 = qt * 64;
    const int m0w = wid * 16;

    const __half* qp = q + ((size_t)bh * S_ + q0) * HD_;
    const __half* kb = k + (size_t)bh * S_ * HD_;
    const __half* vb = v + (size_t)bh * S_ * HD_;

    for (int t = tid; t < 64 * 16; t += 128) {
        int r = t >> 4, c = (t & 15) * 8;
        *(uint4*)&Qs2[r * QST + c / 2] = *(const uint4*)&qp[r * HD_ + c];
    }

    float oacc[16][4];
    #pragma unroll
    for (int ni = 0; ni < 16; ni++)
        #pragma unroll
        for (int u = 0; u < 4; u++) oacc[ni][u] = 0.f;
    float mx0 = -1e30f, mx1 = -1e30f, ls0 = 0.f, ls1 = 0.f;

    const int nkv = qt + 1;
    for (int kt = 0; kt < nkv; kt++) {
        const int k0 = kt * 64;
        __syncthreads();
        const __half* kp = kb + (size_t)k0 * HD_;
        const __half* vp = vb + (size_t)k0 * HD_;
        for (int t = tid; t < 64 * 16; t += 128) {
            int r = t >> 4, c = (t & 15) * 8;
            *(uint4*)&Ks2[r * QST + c / 2] = *(const uint4*)&kp[r * HD_ + c];
        }
        for (int t = tid; t < 32 * 32; t += 128) {
            int s2 = t >> 5, c = (t & 31) * 4;
            uint2 e = *(const uint2*)&vp[(2 * s2) * HD_ + c];
            uint2 o = *(const uint2*)&vp[(2 * s2 + 1) * HD_ + c];
            uint4 u;
            u.x = __byte_perm(e.x, o.x, 0x5410);
            u.y = __byte_perm(e.x, o.x, 0x7632);
            u.z = __byte_perm(e.y, o.y, 0x5410);
            u.w = __byte_perm(e.y, o.y, 0x7632);
            *(uint4*)&Vs2[s2 * VST + c] = u;
        }
        __syncthreads();

        float sacc[8][4];
        #pragma unroll
        for (int ni = 0; ni < 8; ni++)
            #pragma unroll
            for (int u = 0; u < 4; u++) sacc[ni][u] = 0.f;

        #pragma unroll
        for (int ks = 0; ks < 8; ks++) {
            const int kw = ks * 8;
            unsigned a0 = Qs2[(m0w + gid) * QST + kw + tig];
            unsigned a1 = Qs2[(m0w + gid + 8) * QST + kw + tig];
            unsigned a2 = Qs2[(m0w + gid) * QST + kw + tig + 4];
            unsigned a3 = Qs2[(m0w + gid + 8) * QST + kw + tig + 4];
            #pragma unroll
            for (int ni = 0; ni < 8; ni++) {
                unsigned b0 = Ks2[(ni * 8 + gid) * QST + kw + tig];
                unsigned b1 = Ks2[(ni * 8 + gid) * QST + kw + tig + 4];
                MMA_F16(sacc[ni], a0, a1, a2, a3, b0, b1);
            }
        }

        if (kt == nkv - 1) {
            const int row0 = q0 + m0w + gid;
            #pragma unroll
            for (int ni = 0; ni < 8; ni++) {
                const int col = k0 + ni * 8 + tig * 2;
                if (col > row0)     sacc[ni][0] = -1e30f;
                if (col + 1 > row0) sacc[ni][1] = -1e30f;
                if (col > row0 + 8)     sacc[ni][2] = -1e30f;
                if (col + 1 > row0 + 8) sacc[ni][3] = -1e30f;
            }
        }

        float rm0 = -1e30f, rm1 = -1e30f;
        #pragma unroll
        for (int ni = 0; ni < 8; ni++) {
            rm0 = fmaxf(rm0, fmaxf(sacc[ni][0], sacc[ni][1]));
            rm1 = fmaxf(rm1, fmaxf(sacc[ni][2], sacc[ni][3]));
        }
        rm0 = fmaxf(rm0, __shfl_xor_sync(0xffffffffu, rm0, 1));
        rm0 = fmaxf(rm0, __shfl_xor_sync(0xffffffffu, rm0, 2));
        rm1 = fmaxf(rm1, __shfl_xor_sync(0xffffffffu, rm1, 1));
        rm1 = fmaxf(rm1, __shfl_xor_sync(0xffffffffu, rm1, 2));

        const float mn0 = fmaxf(mx0, rm0), mn1 = fmaxf(mx1, rm1);
        const float f0 = __expf(mx0 - mn0), f1 = __expf(mx1 - mn1);
        float rs0 = 0.f, rs1 = 0.f;
        #pragma unroll
        for (int ni = 0; ni < 8; ni++) {
            float p0 = __expf(sacc[ni][0] - mn0);
            float p1 = __expf(sacc[ni][1] - mn0);
            float p2 = __expf(sacc[ni][2] - mn1);
            float p3 = __expf(sacc[ni][3] - mn1);
            sacc[ni][0] = p0; sacc[ni][1] = p1;
            sacc[ni][2] = p2; sacc[ni][3] = p3;
            rs0 += p0 + p1; rs1 += p2 + p3;
        }
        rs0 += __shfl_xor_sync(0xffffffffu, rs0, 1);
        rs0 += __shfl_xor_sync(0xffffffffu, rs0, 2);
        rs1 += __shfl_xor_sync(0xffffffffu, rs1, 1);
        rs1 += __shfl_xor_sync(0xffffffffu, rs1, 2);
        ls0 = ls0 * f0 + rs0; ls1 = ls1 * f1 + rs1;
        mx0 = mn0; mx1 = mn1;

        #pragma unroll
        for (int ni = 0; ni < 16; ni++) {
            oacc[ni][0] *= f0; oacc[ni][1] *= f0;
            oacc[ni][2] *= f1; oacc[ni][3] *= f1;
        }

        #pragma unroll
        for (int j = 0; j < 4; j++) {
            unsigned pa0 = h2u(sacc[2 * j][0], sacc[2 * j][1]);
            unsigned pa1 = h2u(sacc[2 * j][2], sacc[2 * j][3]);
            unsigned pa2 = h2u(sacc[2 * j + 1][0], sacc[2 * j + 1][1]);
            unsigned pa3 = h2u(sacc[2 * j + 1][2], sacc[2 * j + 1][3]);
            #pragma unroll
            for (int ni = 0; ni < 16; ni++) {
                const int nc = ni * 8 + gid;
                unsigned b0 = Vs2[(8 * j + tig) * VST + nc];
                unsigned b1 = Vs2[(8 * j + 4 + tig) * VST + nc];
                MMA_F16(oacc[ni], pa0, pa1, pa2, pa3, b0, b1);
            }
        }
    }

    const float inv0 = 1.f / ls0, inv1 = 1.f / ls1;
    const int b = bh >> 4, h = bh & 15;
    const int s0 = q0 + m0w + gid;
    #pragma unroll
    for (int ni = 0; ni < 16; ni++) {
        const int col = ni * 8 + tig * 2;
        *(unsigned*)&ctx[(size_t)(b * S_ + s0) * DM_ + h * HD_ + col] =
            h2u(oacc[ni][0] * inv0, oacc[ni][1] * inv0);
        *(unsigned*)&ctx[(size_t)(b * S_ + s0 + 8) * DM_ + h * HD_ + col] =
            h2u(oacc[ni][2] * inv1, oacc[ni][3] * inv1);
    }
}

// ---------------------------------------------------------------------------
// Launch
// ---------------------------------------------------------------------------
extern "C" void kernel_launch(void* const* d_in, const int* in_sizes, int n_in,
                              void* d_out, int out_size)
{
    const float* hs = (const float*)d_in[0];
    const float* Wq = (const float*)d_in[1];
    const float* bq = (const float*)d_in[2];
    const float* Wk = (const float*)d_in[3];
    const float* bk = (const float*)d_in[4];
    const float* Wv = (const float*)d_in[5];
    const float* bv = (const float*)d_in[6];
    const float* Wo = (const float*)d_in[7];
    const float* bo = (const float*)d_in[8];
    float* out = (float*)d_out;

    __half *qd, *kd, *vd, *ctxd, *ahd;
    unsigned* wtd;
    cudaGetSymbolAddress((void**)&qd,   g_qh);
    cudaGetSymbolAddress((void**)&kd,   g_kh);
    cudaGetSymbolAddress((void**)&vd,   g_vh);
    cudaGetSymbolAddress((void**)&ctxd, g_ctxh);
    cudaGetSymbolAddress((void**)&ahd,  g_ah);
    cudaGetSymbolAddress((void**)&wtd,  g_wt);
    unsigned* wq_t = wtd + 0 * (size_t)(DM_ / 2) * DM_;
    unsigned* wk_t = wtd + 1 * (size_t)(DM_ / 2) * DM_;
    unsigned* wv_t = wtd + 2 * (size_t)(DM_ / 2) * DM_;
    unsigned* wo_t = wtd + 3 * (size_t)(DM_ / 2) * DM_;

    const int gemm_smem = 3 * STAGEB;                       // 56832
    const int attn_smem = (2 * QWORDS + 32 * VST) * (int)sizeof(unsigned);
    static int smem_set = 0;
    if (!smem_set) {
        cudaFuncSetAttribute(hgemm2_kernel,
                             cudaFuncAttributeMaxDynamicSharedMemorySize,
                             gemm_smem);
        cudaFuncSetAttribute(attn_h_kernel,
                             cudaFuncAttributeMaxDynamicSharedMemorySize,
                             attn_smem);
        smem_set = 1;
    }

    rope_table_kernel<<<(S_ * (HD_ / 2) + 255) / 256, 256>>>();

    const int na8 = BS_ * DM_ / 8;
    const int nw  = (GK / 2) * (GN / 4);
    cvt_a_kernel<<<(na8 + 255) / 256, 256>>>(hs, ahd, na8);
    dim3 wgrid((nw + 255) / 256, 1, 4);
    cvt_w_kernel<<<wgrid, 256>>>(Wq, Wk, Wv, Wo, wtd);

    dim3 qkvgrid(GN / 128, 4096 / 128, 3);
    hgemm2_kernel<<<qkvgrid, 256, gemm_smem>>>(
        ahd, wq_t, wk_t, wv_t, bq, bk, bv, qd, kd, vd, -1);

    dim3 agrid(S_ / 64, B_ * NH_);
    attn_h_kernel<<<agrid, 128, attn_smem>>>(qd, kd, vd, ctxd);

    dim3 ogrid(GN / 128, 4096 / 128, 1);
    hgemm2_kernel<<<ogrid, 256, gemm_smem>>>(
        ctxd, wo_t, nullptr, nullptr, bo, nullptr, nullptr, out, nullptr,
        nullptr, 2);
}